// round 2
// baseline (speedup 1.0000x reference)
#include <cuda_runtime.h>
#include <mma.h>

using namespace nvcuda;

#define ASCALE 0.125f

// hi/lo tf32 splits of (q*scale, k, v), laid out [s][bwh][t][d]
__device__ __align__(128) float g_h[3u * 1536u * 256u * 64u];
__device__ __align__(128) float g_l[3u * 1536u * 256u * 64u];
__device__ __align__(128) float g_att[1536u * 256u * 64u];

// ---------------------------------------------------------------------------
// Kernel 1: fused window-permute + QKV GEMM (TF32 wmma, NT)
// Epilogue writes hi/lo tf32 split (Q pre-scaled by ASCALE).
// ---------------------------------------------------------------------------
__global__ __launch_bounds__(128) void qkv_gemm(const float* __restrict__ x,
                                                const float* __restrict__ w) {
    __shared__ float As[64][20];
    __shared__ float Bs[64][20];
    __shared__ float Cs[64][64];
    __shared__ const float* Arow[64];

    const int tid = threadIdx.x;
    const int bx = blockIdx.x;   // 0..35  (col tiles over 2304)
    const int by = blockIdx.y;   // 0..511 (row tiles over 32768)

    if (tid < 64) {
        int gm = by * 64 + tid;
        int b = gm >> 12;
        int p = gm & 4095;
        int wdw = p >> 8;
        int t = p & 255;
        int wr = wdw >> 2, wc = wdw & 3, r = t >> 4, c = t & 15;
        int orig = ((wr * 16 + r) << 6) + (wc * 16 + c);
        Arow[tid] = x + (size_t)(b * 4096 + orig) * 768;
    }

    const int warp = tid >> 5;
    const int wr2 = warp >> 1, wc2 = warp & 1;

    wmma::fragment<wmma::accumulator, 16, 16, 8, float> acc[2][2];
#pragma unroll
    for (int i = 0; i < 2; i++)
#pragma unroll
        for (int j = 0; j < 2; j++) wmma::fill_fragment(acc[i][j], 0.0f);

    __syncthreads();

    const int n0 = bx * 64;

    for (int k0 = 0; k0 < 768; k0 += 16) {
#pragma unroll
        for (int rep = 0; rep < 2; rep++) {
            int ii = tid + rep * 128;
            int row = ii >> 2;
            int kq = (ii & 3) << 2;
            *(float4*)&As[row][kq] = *(const float4*)(Arow[row] + k0 + kq);
            *(float4*)&Bs[row][kq] = *(const float4*)(w + (size_t)(n0 + row) * 768 + k0 + kq);
        }
        __syncthreads();

#pragma unroll
        for (int ks = 0; ks < 16; ks += 8) {
            wmma::fragment<wmma::matrix_a, 16, 16, 8, wmma::precision::tf32, wmma::row_major> af[2];
            wmma::fragment<wmma::matrix_b, 16, 16, 8, wmma::precision::tf32, wmma::col_major> bf[2];
#pragma unroll
            for (int i = 0; i < 2; i++) {
                wmma::load_matrix_sync(af[i], &As[wr2 * 32 + i * 16][ks], 20);
#pragma unroll
                for (int e = 0; e < af[i].num_elements; e++)
                    af[i].x[e] = wmma::__float_to_tf32(af[i].x[e]);
            }
#pragma unroll
            for (int j = 0; j < 2; j++) {
                wmma::load_matrix_sync(bf[j], &Bs[wc2 * 32 + j * 16][ks], 20);
#pragma unroll
                for (int e = 0; e < bf[j].num_elements; e++)
                    bf[j].x[e] = wmma::__float_to_tf32(bf[j].x[e]);
            }
#pragma unroll
            for (int i = 0; i < 2; i++)
#pragma unroll
                for (int j = 0; j < 2; j++)
                    wmma::mma_sync(acc[i][j], af[i], bf[j], acc[i][j]);
        }
        __syncthreads();
    }

#pragma unroll
    for (int i = 0; i < 2; i++)
#pragma unroll
        for (int j = 0; j < 2; j++)
            wmma::store_matrix_sync(&Cs[wr2 * 32 + i * 16][wc2 * 32 + j * 16], acc[i][j],
                                    64, wmma::mem_row_major);
    __syncthreads();

    int s = n0 / 768;
    int h = (n0 - s * 768) >> 6;
    int gm0 = by * 64;
    int b = gm0 >> 12;
    int p = gm0 & 4095;
    int wdw = p >> 8;
    int t0 = p & 255;
    size_t off = ((size_t)(s * 1536 + (b * 16 + wdw) * 12 + h) * 256 + t0) * 64;
    float* dsth = g_h + off;
    float* dstl = g_l + off;
    const float sc = (s == 0) ? ASCALE : 1.0f;

    for (int i = tid; i < 1024; i += 128) {
        int rr = i >> 4;
        int cc = (i & 15) << 2;
        float4 v = *(float4*)&Cs[rr][cc];
        v.x *= sc; v.y *= sc; v.z *= sc; v.w *= sc;
        float4 h4, l4;
        h4.x = wmma::__float_to_tf32(v.x); l4.x = wmma::__float_to_tf32(v.x - h4.x);
        h4.y = wmma::__float_to_tf32(v.y); l4.y = wmma::__float_to_tf32(v.y - h4.y);
        h4.z = wmma::__float_to_tf32(v.z); l4.z = wmma::__float_to_tf32(v.z - h4.z);
        h4.w = wmma::__float_to_tf32(v.w); l4.w = wmma::__float_to_tf32(v.w - h4.w);
        *(float4*)(dsth + rr * 64 + cc) = h4;
        *(float4*)(dstl + rr * 64 + cc) = l4;
    }
}

// ---------------------------------------------------------------------------
// Kernel 2: tensor-core windowed attention (3xTF32, softmax without max).
// Grid: 3072 blocks = bwh * 2 panels of 128 queries. 4 warps, 32 q/warp.
// Per chunk of 32 keys: S via 3-pass tf32 MMA, exp on acc frags, P hi/lo
// through warp-private smem, P.V via 3-pass MMA, row-sum via ones-column.
// ---------------------------------------------------------------------------
__global__ __launch_bounds__(128, 2) void attn_tc() {
    extern __shared__ float sm[];
    float* Kh = sm;                    // 32 x 72
    float* Kl = Kh + 32 * 72;
    float* Vh = Kl + 32 * 72;          // 32 x 80 (cols 64..79: ones tile)
    float* Vl = Vh + 32 * 80;
    float* Pw = Vl + 32 * 80;          // 4 warps x 32 x 68

    const int blk = blockIdx.x;
    const int bwh = blk >> 1, panel = blk & 1;
    const int tid = threadIdx.x, warp = tid >> 5, lane = tid & 31;
    float* Ps = Pw + warp * (32 * 68);

    const size_t qoff = (size_t)bwh * 16384 + (size_t)(panel * 128 + warp * 32) * 64;
    const float* qh = g_h + qoff;
    const float* ql = g_l + qoff;
    const float* kh = g_h + (size_t)(1536 + bwh) * 16384;
    const float* kl = g_l + (size_t)(1536 + bwh) * 16384;
    const float* vh = g_h + (size_t)(3072 + bwh) * 16384;
    const float* vl = g_l + (size_t)(3072 + bwh) * 16384;

    // ones tile (col 64 = 1, rest 0); untouched by chunk staging
    for (int i = tid; i < 32 * 16; i += 128) {
        int r = i >> 4, c = i & 15;
        Vh[r * 80 + 64 + c] = (c == 0) ? 1.0f : 0.0f;
        Vl[r * 80 + 64 + c] = 0.0f;
    }

    wmma::fragment<wmma::accumulator, 16, 16, 8, float> O[2][5];
#pragma unroll
    for (int rt = 0; rt < 2; rt++)
#pragma unroll
        for (int ct = 0; ct < 5; ct++) wmma::fill_fragment(O[rt][ct], 0.0f);

    for (int c = 0; c < 8; c++) {
        __syncthreads();
        // stage 32-key chunk of K,V hi/lo
        for (int i = tid; i < 512; i += 128) {
            int r = i >> 4;
            int cc = (i & 15) << 2;
            int g = c * 2048 + r * 64 + cc;
            *(float4*)&Kh[r * 72 + cc] = *(const float4*)(kh + g);
            *(float4*)&Kl[r * 72 + cc] = *(const float4*)(kl + g);
            *(float4*)&Vh[r * 80 + cc] = *(const float4*)(vh + g);
            *(float4*)&Vl[r * 80 + cc] = *(const float4*)(vl + g);
        }
        __syncthreads();

        // S (32q x 32k) = Qhi*Khi + Qhi*Klo + Qlo*Khi
        wmma::fragment<wmma::accumulator, 16, 16, 8, float> S[2][2];
#pragma unroll
        for (int rt = 0; rt < 2; rt++)
#pragma unroll
            for (int ct = 0; ct < 2; ct++) wmma::fill_fragment(S[rt][ct], 0.0f);

#pragma unroll 2
        for (int ks = 0; ks < 8; ks++) {
            wmma::fragment<wmma::matrix_b, 16, 16, 8, wmma::precision::tf32, wmma::col_major> Bh2[2], Bl2[2];
#pragma unroll
            for (int ct = 0; ct < 2; ct++) {
                wmma::load_matrix_sync(Bh2[ct], &Kh[ct * 16 * 72 + ks * 8], 72);
                wmma::load_matrix_sync(Bl2[ct], &Kl[ct * 16 * 72 + ks * 8], 72);
            }
#pragma unroll
            for (int rt = 0; rt < 2; rt++) {
                wmma::fragment<wmma::matrix_a, 16, 16, 8, wmma::precision::tf32, wmma::row_major> Ah, Al;
                wmma::load_matrix_sync(Ah, qh + rt * 16 * 64 + ks * 8, 64);
                wmma::load_matrix_sync(Al, ql + rt * 16 * 64 + ks * 8, 64);
#pragma unroll
                for (int ct = 0; ct < 2; ct++) {
                    wmma::mma_sync(S[rt][ct], Ah, Bh2[ct], S[rt][ct]);
                    wmma::mma_sync(S[rt][ct], Ah, Bl2[ct], S[rt][ct]);
                    wmma::mma_sync(S[rt][ct], Al, Bh2[ct], S[rt][ct]);
                }
            }
        }

        // P = exp(S): elementwise on fragments; split hi/lo
        wmma::fragment<wmma::accumulator, 16, 16, 8, float> Plo[2][2];
#pragma unroll
        for (int rt = 0; rt < 2; rt++)
#pragma unroll
            for (int ct = 0; ct < 2; ct++)
#pragma unroll
                for (int e = 0; e < 8; e++) {
                    float p = __expf(S[rt][ct].x[e]);
                    float hh = wmma::__float_to_tf32(p);
                    S[rt][ct].x[e] = hh;
                    Plo[rt][ct].x[e] = wmma::__float_to_tf32(p - hh);
                }

#pragma unroll
        for (int rt = 0; rt < 2; rt++)
#pragma unroll
            for (int ct = 0; ct < 2; ct++)
                wmma::store_matrix_sync(&Ps[rt * 16 * 68 + ct * 16], S[rt][ct], 68, wmma::mem_row_major);
        __syncwarp();

        // O += Phi*Vhi (incl ones) + Phi*Vlo
#pragma unroll
        for (int ks = 0; ks < 4; ks++) {
            wmma::fragment<wmma::matrix_b, 16, 16, 8, wmma::precision::tf32, wmma::row_major> Bv[5], Bvl[4];
#pragma unroll
            for (int ct = 0; ct < 5; ct++)
                wmma::load_matrix_sync(Bv[ct], &Vh[ks * 8 * 80 + ct * 16], 80);
#pragma unroll
            for (int ct = 0; ct < 4; ct++)
                wmma::load_matrix_sync(Bvl[ct], &Vl[ks * 8 * 80 + ct * 16], 80);
#pragma unroll
            for (int rt = 0; rt < 2; rt++) {
                wmma::fragment<wmma::matrix_a, 16, 16, 8, wmma::precision::tf32, wmma::row_major> Ap;
                wmma::load_matrix_sync(Ap, &Ps[rt * 16 * 68 + ks * 8], 68);
#pragma unroll
                for (int ct = 0; ct < 5; ct++) wmma::mma_sync(O[rt][ct], Ap, Bv[ct], O[rt][ct]);
#pragma unroll
                for (int ct = 0; ct < 4; ct++) wmma::mma_sync(O[rt][ct], Ap, Bvl[ct], O[rt][ct]);
            }
        }
        __syncwarp();

#pragma unroll
        for (int rt = 0; rt < 2; rt++)
#pragma unroll
            for (int ct = 0; ct < 2; ct++)
                wmma::store_matrix_sync(&Ps[rt * 16 * 68 + ct * 16], Plo[rt][ct], 68, wmma::mem_row_major);
        __syncwarp();

        // O += Plo*Vhi (incl ones)
#pragma unroll
        for (int ks = 0; ks < 4; ks++) {
            wmma::fragment<wmma::matrix_b, 16, 16, 8, wmma::precision::tf32, wmma::row_major> Bv[5];
#pragma unroll
            for (int ct = 0; ct < 5; ct++)
                wmma::load_matrix_sync(Bv[ct], &Vh[ks * 8 * 80 + ct * 16], 80);
#pragma unroll
            for (int rt = 0; rt < 2; rt++) {
                wmma::fragment<wmma::matrix_a, 16, 16, 8, wmma::precision::tf32, wmma::row_major> Ap;
                wmma::load_matrix_sync(Ap, &Ps[rt * 16 * 68 + ks * 8], 68);
#pragma unroll
                for (int ct = 0; ct < 5; ct++) wmma::mma_sync(O[rt][ct], Ap, Bv[ct], O[rt][ct]);
            }
        }
    }

    __syncthreads();   // all warps done with K/V smem; reuse for row sums

    float* lb = sm + warp * 512;   // 32 rows x 16, stride 16
#pragma unroll
    for (int rt = 0; rt < 2; rt++)
        wmma::store_matrix_sync(lb + rt * 256, O[rt][4], 16, wmma::mem_row_major);
#pragma unroll
    for (int rt = 0; rt < 2; rt++)
#pragma unroll
        for (int ct = 0; ct < 4; ct++)
            wmma::store_matrix_sync(&Ps[rt * 16 * 68 + ct * 16], O[rt][ct], 68, wmma::mem_row_major);
    __syncwarp();

    float* op = g_att + (size_t)bwh * 16384 + (size_t)(panel * 128 + warp * 32) * 64;
    const int r = lane;
    const float linv = 1.0f / lb[r * 16];
#pragma unroll
    for (int cc = 0; cc < 64; cc += 4) {
        float4 v = *(float4*)&Ps[r * 68 + cc];
        v.x *= linv; v.y *= linv; v.z *= linv; v.w *= linv;
        *(float4*)(op + r * 64 + cc) = v;
    }
}

// ---------------------------------------------------------------------------
// Kernel 3: fused inverse-permute + head-merge + proj GEMM (TF32 wmma) + bias
// ---------------------------------------------------------------------------
__global__ __launch_bounds__(128) void proj_gemm(const float* __restrict__ w,
                                                 const float* __restrict__ bias,
                                                 float* __restrict__ out) {
    __shared__ float As[64][20];
    __shared__ float Bs[64][20];
    __shared__ float Cs[64][64];
    __shared__ const float* Abase[64];

    const int tid = threadIdx.x;
    const int bx = blockIdx.x;
    const int by = blockIdx.y;

    if (tid < 64) {
        int gm = by * 64 + tid;
        int b = gm >> 12;
        int n = gm & 4095;
        int row = n >> 6, col = n & 63;
        int wr = row >> 4, r = row & 15, wc = col >> 4, c = col & 15;
        int wdw = wr * 4 + wc;
        int t = r * 16 + c;
        Abase[tid] = g_att + ((size_t)(b * 16 + wdw) * 12 * 256 + t) * 64;
    }

    const int warp = tid >> 5;
    const int wr2 = warp >> 1, wc2 = warp & 1;

    wmma::fragment<wmma::accumulator, 16, 16, 8, float> acc[2][2];
#pragma unroll
    for (int i = 0; i < 2; i++)
#pragma unroll
        for (int j = 0; j < 2; j++) wmma::fill_fragment(acc[i][j], 0.0f);

    __syncthreads();

    const int n0 = bx * 64;

    for (int k0 = 0; k0 < 768; k0 += 16) {
#pragma unroll
        for (int rep = 0; rep < 2; rep++) {
            int ii = tid + rep * 128;
            int row = ii >> 2;
            int kq = (ii & 3) << 2;
            int k = k0 + kq;
            const float* src = Abase[row] + (k >> 6) * 16384 + (k & 63);
            *(float4*)&As[row][kq] = *(const float4*)src;
            *(float4*)&Bs[row][kq] = *(const float4*)(w + (size_t)(n0 + row) * 768 + k0 + kq);
        }
        __syncthreads();

#pragma unroll
        for (int ks = 0; ks < 16; ks += 8) {
            wmma::fragment<wmma::matrix_a, 16, 16, 8, wmma::precision::tf32, wmma::row_major> af[2];
            wmma::fragment<wmma::matrix_b, 16, 16, 8, wmma::precision::tf32, wmma::col_major> bf[2];
#pragma unroll
            for (int i = 0; i < 2; i++) {
                wmma::load_matrix_sync(af[i], &As[wr2 * 32 + i * 16][ks], 20);
#pragma unroll
                for (int e = 0; e < af[i].num_elements; e++)
                    af[i].x[e] = wmma::__float_to_tf32(af[i].x[e]);
            }
#pragma unroll
            for (int j = 0; j < 2; j++) {
                wmma::load_matrix_sync(bf[j], &Bs[wc2 * 32 + j * 16][ks], 20);
#pragma unroll
                for (int e = 0; e < bf[j].num_elements; e++)
                    bf[j].x[e] = wmma::__float_to_tf32(bf[j].x[e]);
            }
#pragma unroll
            for (int i = 0; i < 2; i++)
#pragma unroll
                for (int j = 0; j < 2; j++)
                    wmma::mma_sync(acc[i][j], af[i], bf[j], acc[i][j]);
        }
        __syncthreads();
    }

#pragma unroll
    for (int i = 0; i < 2; i++)
#pragma unroll
        for (int j = 0; j < 2; j++)
            wmma::store_matrix_sync(&Cs[wr2 * 32 + i * 16][wc2 * 32 + j * 16], acc[i][j],
                                    64, wmma::mem_row_major);
    __syncthreads();

    float* dst = out + (size_t)(by * 64) * 768 + n0;
    for (int i = tid; i < 1024; i += 128) {
        int rr = i >> 4;
        int cc = (i & 15) << 2;
        float4 v = *(float4*)&Cs[rr][cc];
        v.x += bias[n0 + cc + 0];
        v.y += bias[n0 + cc + 1];
        v.z += bias[n0 + cc + 2];
        v.w += bias[n0 + cc + 3];
        *(float4*)(dst + (size_t)rr * 768 + cc) = v;
    }
}

// ---------------------------------------------------------------------------
extern "C" void kernel_launch(void* const* d_in, const int* in_sizes, int n_in,
                              void* d_out, int out_size) {
    const float* x      = (const float*)d_in[0];
    const float* qkv_w  = (const float*)d_in[1];
    const float* proj_w = (const float*)d_in[2];
    const float* proj_b = (const float*)d_in[3];
    float* out = (float*)d_out;

    cudaFuncSetAttribute(attn_tc, cudaFuncAttributeMaxDynamicSharedMemorySize, 73728);

    dim3 g1(36, 512);
    qkv_gemm<<<g1, 128>>>(x, qkv_w);

    attn_tc<<<3072, 128, 73728>>>();

    dim3 g2(12, 512);
    proj_gemm<<<g2, 128>>>(proj_w, proj_b, out);
}

// round 5
// speedup vs baseline: 1.2312x; 1.2312x over previous
#include <cuda_runtime.h>
#include <mma.h>

using namespace nvcuda;

#define ASCALE 0.125f

// qkv staged as [s][bwh][t][d] fp32 (Q pre-scaled); attention out [bwh][t][d]
__device__ __align__(128) float g_qkv[3u * 1536u * 256u * 64u];
__device__ __align__(128) float g_att[1536u * 256u * 64u];

// ---------------------------------------------------------------------------
// Kernel 1: fused window-permute + QKV GEMM (TF32 wmma, NT)
// ---------------------------------------------------------------------------
__global__ __launch_bounds__(128) void qkv_gemm(const float* __restrict__ x,
                                                const float* __restrict__ w) {
    __shared__ float As[64][20];
    __shared__ float Bs[64][20];
    __shared__ float Cs[64][64];
    __shared__ const float* Arow[64];

    const int tid = threadIdx.x;
    const int bx = blockIdx.x;   // 0..35
    const int by = blockIdx.y;   // 0..511

    if (tid < 64) {
        int gm = by * 64 + tid;
        int b = gm >> 12;
        int p = gm & 4095;
        int wdw = p >> 8;
        int t = p & 255;
        int wr = wdw >> 2, wc = wdw & 3, r = t >> 4, c = t & 15;
        int orig = ((wr * 16 + r) << 6) + (wc * 16 + c);
        Arow[tid] = x + (size_t)(b * 4096 + orig) * 768;
    }

    const int warp = tid >> 5;
    const int wr2 = warp >> 1, wc2 = warp & 1;

    wmma::fragment<wmma::accumulator, 16, 16, 8, float> acc[2][2];
#pragma unroll
    for (int i = 0; i < 2; i++)
#pragma unroll
        for (int j = 0; j < 2; j++) wmma::fill_fragment(acc[i][j], 0.0f);

    __syncthreads();

    const int n0 = bx * 64;

    for (int k0 = 0; k0 < 768; k0 += 16) {
#pragma unroll
        for (int rep = 0; rep < 2; rep++) {
            int ii = tid + rep * 128;
            int row = ii >> 2;
            int kq = (ii & 3) << 2;
            *(float4*)&As[row][kq] = *(const float4*)(Arow[row] + k0 + kq);
            *(float4*)&Bs[row][kq] = *(const float4*)(w + (size_t)(n0 + row) * 768 + k0 + kq);
        }
        __syncthreads();

#pragma unroll
        for (int ks = 0; ks < 16; ks += 8) {
            wmma::fragment<wmma::matrix_a, 16, 16, 8, wmma::precision::tf32, wmma::row_major> af[2];
            wmma::fragment<wmma::matrix_b, 16, 16, 8, wmma::precision::tf32, wmma::col_major> bf[2];
#pragma unroll
            for (int i = 0; i < 2; i++) {
                wmma::load_matrix_sync(af[i], &As[wr2 * 32 + i * 16][ks], 20);
#pragma unroll
                for (int e = 0; e < af[i].num_elements; e++)
                    af[i].x[e] = wmma::__float_to_tf32(af[i].x[e]);
            }
#pragma unroll
            for (int j = 0; j < 2; j++) {
                wmma::load_matrix_sync(bf[j], &Bs[wc2 * 32 + j * 16][ks], 20);
#pragma unroll
                for (int e = 0; e < bf[j].num_elements; e++)
                    bf[j].x[e] = wmma::__float_to_tf32(bf[j].x[e]);
            }
#pragma unroll
            for (int i = 0; i < 2; i++)
#pragma unroll
                for (int j = 0; j < 2; j++)
                    wmma::mma_sync(acc[i][j], af[i], bf[j], acc[i][j]);
        }
        __syncthreads();
    }

#pragma unroll
    for (int i = 0; i < 2; i++)
#pragma unroll
        for (int j = 0; j < 2; j++)
            wmma::store_matrix_sync(&Cs[wr2 * 32 + i * 16][wc2 * 32 + j * 16], acc[i][j],
                                    64, wmma::mem_row_major);
    __syncthreads();

    int s = n0 / 768;
    int h = (n0 - s * 768) >> 6;
    int gm0 = by * 64;
    int b = gm0 >> 12;
    int p = gm0 & 4095;
    int wdw = p >> 8;
    int t0 = p & 255;
    float* dst = g_qkv + ((size_t)(s * 1536 + (b * 16 + wdw) * 12 + h) * 256 + t0) * 64;
    const float sc = (s == 0) ? ASCALE : 1.0f;

    for (int i = tid; i < 1024; i += 128) {
        int rr = i >> 4;
        int cc = (i & 15) << 2;
        float4 v = *(float4*)&Cs[rr][cc];
        v.x *= sc; v.y *= sc; v.z *= sc; v.w *= sc;
        *(float4*)(dst + rr * 64 + cc) = v;
    }
}

// ---------------------------------------------------------------------------
// Kernel 2: tensor-core windowed attention, single-pass TF32.
// Block = (bwh, panel of 128 queries). 4 warps, 32 q/warp.
// Q staged to smem once (tf32); per 32-key chunk: S = Q.K^T (1 pass),
// P = exp(S) on fragments, P.V (1 pass) with ones-column giving row sums.
// ---------------------------------------------------------------------------
__global__ __launch_bounds__(128, 2) void attn_tc() {
    extern __shared__ float sm[];
    float* Qs = sm;                    // 128 x 72
    float* Ks = Qs + 128 * 72;         // 32 x 72
    float* Vs = Ks + 32 * 72;          // 32 x 80 (cols 64..79: ones tile)
    float* Pw = Vs + 32 * 80;          // 4 warps x 32 x 68

    const int blk = blockIdx.x;
    const int bwh = blk >> 1, panel = blk & 1;
    const int tid = threadIdx.x, warp = tid >> 5, lane = tid & 31;
    float* Ps = Pw + warp * (32 * 68);

    const float* qp = g_qkv + (size_t)bwh * 16384 + (size_t)(panel * 128) * 64;
    const float* kp = g_qkv + (size_t)(1536 + bwh) * 16384;
    const float* vp = g_qkv + (size_t)(3072 + bwh) * 16384;

    // stage Q panel (tf32-rounded)
    for (int i = tid; i < 2048; i += 128) {        // 2048 float4 = 128x64
        int r = i >> 4;
        int cc = (i & 15) << 2;
        float4 v = *(const float4*)(qp + r * 64 + cc);
        v.x = wmma::__float_to_tf32(v.x);
        v.y = wmma::__float_to_tf32(v.y);
        v.z = wmma::__float_to_tf32(v.z);
        v.w = wmma::__float_to_tf32(v.w);
        *(float4*)&Qs[r * 72 + cc] = v;
    }
    // ones tile (col 64 = 1, rest 0)
    for (int i = tid; i < 32 * 16; i += 128) {
        int r = i >> 4, c = i & 15;
        Vs[r * 80 + 64 + c] = (c == 0) ? 1.0f : 0.0f;
    }

    wmma::fragment<wmma::accumulator, 16, 16, 8, float> O[2][5];
#pragma unroll
    for (int rt = 0; rt < 2; rt++)
#pragma unroll
        for (int ct = 0; ct < 5; ct++) wmma::fill_fragment(O[rt][ct], 0.0f);

    for (int c = 0; c < 8; c++) {
        __syncthreads();
        for (int i = tid; i < 512; i += 128) {     // 32x64 per buffer
            int r = i >> 4;
            int cc = (i & 15) << 2;
            int g = c * 2048 + r * 64 + cc;
            float4 kv = *(const float4*)(kp + g);
            kv.x = wmma::__float_to_tf32(kv.x);
            kv.y = wmma::__float_to_tf32(kv.y);
            kv.z = wmma::__float_to_tf32(kv.z);
            kv.w = wmma::__float_to_tf32(kv.w);
            *(float4*)&Ks[r * 72 + cc] = kv;
            float4 vv = *(const float4*)(vp + g);
            vv.x = wmma::__float_to_tf32(vv.x);
            vv.y = wmma::__float_to_tf32(vv.y);
            vv.z = wmma::__float_to_tf32(vv.z);
            vv.w = wmma::__float_to_tf32(vv.w);
            *(float4*)&Vs[r * 80 + cc] = vv;
        }
        __syncthreads();

        // S (32q x 32k) = Q.K^T, single pass
        wmma::fragment<wmma::accumulator, 16, 16, 8, float> S[2][2];
#pragma unroll
        for (int rt = 0; rt < 2; rt++)
#pragma unroll
            for (int ct = 0; ct < 2; ct++) wmma::fill_fragment(S[rt][ct], 0.0f);

#pragma unroll
        for (int ks = 0; ks < 8; ks++) {
            wmma::fragment<wmma::matrix_b, 16, 16, 8, wmma::precision::tf32, wmma::col_major> Bf[2];
#pragma unroll
            for (int ct = 0; ct < 2; ct++)
                wmma::load_matrix_sync(Bf[ct], &Ks[ct * 16 * 72 + ks * 8], 72);
#pragma unroll
            for (int rt = 0; rt < 2; rt++) {
                wmma::fragment<wmma::matrix_a, 16, 16, 8, wmma::precision::tf32, wmma::row_major> Af;
                wmma::load_matrix_sync(Af, &Qs[(warp * 32 + rt * 16) * 72 + ks * 8], 72);
#pragma unroll
                for (int ct = 0; ct < 2; ct++)
                    wmma::mma_sync(S[rt][ct], Af, Bf[ct], S[rt][ct]);
            }
        }

        // P = exp(S), rounded to tf32, staged via warp-private smem
#pragma unroll
        for (int rt = 0; rt < 2; rt++)
#pragma unroll
            for (int ct = 0; ct < 2; ct++) {
#pragma unroll
                for (int e = 0; e < 8; e++)
                    S[rt][ct].x[e] = wmma::__float_to_tf32(__expf(S[rt][ct].x[e]));
                wmma::store_matrix_sync(&Ps[rt * 16 * 68 + ct * 16], S[rt][ct], 68,
                                        wmma::mem_row_major);
            }
        __syncwarp();

        // O += P.V (V cols 64..79 are the ones tile -> row sums in O[rt][4])
#pragma unroll
        for (int ks = 0; ks < 4; ks++) {
            wmma::fragment<wmma::matrix_b, 16, 16, 8, wmma::precision::tf32, wmma::row_major> Bv[5];
#pragma unroll
            for (int ct = 0; ct < 5; ct++)
                wmma::load_matrix_sync(Bv[ct], &Vs[ks * 8 * 80 + ct * 16], 80);
#pragma unroll
            for (int rt = 0; rt < 2; rt++) {
                wmma::fragment<wmma::matrix_a, 16, 16, 8, wmma::precision::tf32, wmma::row_major> Ap;
                wmma::load_matrix_sync(Ap, &Ps[rt * 16 * 68 + ks * 8], 68);
#pragma unroll
                for (int ct = 0; ct < 5; ct++)
                    wmma::mma_sync(O[rt][ct], Ap, Bv[ct], O[rt][ct]);
            }
        }
    }

    __syncthreads();   // all warps done with shared K/V; reuse smem

    float* lb = sm + warp * 512;   // 32 rows x 16
#pragma unroll
    for (int rt = 0; rt < 2; rt++)
        wmma::store_matrix_sync(lb + rt * 256, O[rt][4], 16, wmma::mem_row_major);
#pragma unroll
    for (int rt = 0; rt < 2; rt++)
#pragma unroll
        for (int ct = 0; ct < 4; ct++)
            wmma::store_matrix_sync(&Ps[rt * 16 * 68 + ct * 16], O[rt][ct], 68,
                                    wmma::mem_row_major);
    __syncwarp();

    float* op = g_att + (size_t)bwh * 16384 + (size_t)(panel * 128 + warp * 32) * 64;
    const int r = lane;
    const float linv = 1.0f / lb[r * 16];
#pragma unroll
    for (int cc = 0; cc < 64; cc += 4) {
        float4 v = *(float4*)&Ps[r * 68 + cc];
        v.x *= linv; v.y *= linv; v.z *= linv; v.w *= linv;
        *(float4*)(op + r * 64 + cc) = v;
    }
}

// ---------------------------------------------------------------------------
// Kernel 3: fused inverse-permute + head-merge + proj GEMM (TF32 wmma) + bias
// ---------------------------------------------------------------------------
__global__ __launch_bounds__(128) void proj_gemm(const float* __restrict__ w,
                                                 const float* __restrict__ bias,
                                                 float* __restrict__ out) {
    __shared__ float As[64][20];
    __shared__ float Bs[64][20];
    __shared__ float Cs[64][64];
    __shared__ const float* Abase[64];

    const int tid = threadIdx.x;
    const int bx = blockIdx.x;
    const int by = blockIdx.y;

    if (tid < 64) {
        int gm = by * 64 + tid;
        int b = gm >> 12;
        int n = gm & 4095;
        int row = n >> 6, col = n & 63;
        int wr = row >> 4, r = row & 15, wc = col >> 4, c = col & 15;
        int wdw = wr * 4 + wc;
        int t = r * 16 + c;
        Abase[tid] = g_att + ((size_t)(b * 16 + wdw) * 12 * 256 + t) * 64;
    }

    const int warp = tid >> 5;
    const int wr2 = warp >> 1, wc2 = warp & 1;

    wmma::fragment<wmma::accumulator, 16, 16, 8, float> acc[2][2];
#pragma unroll
    for (int i = 0; i < 2; i++)
#pragma unroll
        for (int j = 0; j < 2; j++) wmma::fill_fragment(acc[i][j], 0.0f);

    __syncthreads();

    const int n0 = bx * 64;

    for (int k0 = 0; k0 < 768; k0 += 16) {
#pragma unroll
        for (int rep = 0; rep < 2; rep++) {
            int ii = tid + rep * 128;
            int row = ii >> 2;
            int kq = (ii & 3) << 2;
            int k = k0 + kq;
            const float* src = Abase[row] + (k >> 6) * 16384 + (k & 63);
            *(float4*)&As[row][kq] = *(const float4*)src;
            *(float4*)&Bs[row][kq] = *(const float4*)(w + (size_t)(n0 + row) * 768 + k0 + kq);
        }
        __syncthreads();

#pragma unroll
        for (int ks = 0; ks < 16; ks += 8) {
            wmma::fragment<wmma::matrix_a, 16, 16, 8, wmma::precision::tf32, wmma::row_major> af[2];
            wmma::fragment<wmma::matrix_b, 16, 16, 8, wmma::precision::tf32, wmma::col_major> bf[2];
#pragma unroll
            for (int i = 0; i < 2; i++) {
                wmma::load_matrix_sync(af[i], &As[wr2 * 32 + i * 16][ks], 20);
#pragma unroll
                for (int e = 0; e < af[i].num_elements; e++)
                    af[i].x[e] = wmma::__float_to_tf32(af[i].x[e]);
            }
#pragma unroll
            for (int j = 0; j < 2; j++) {
                wmma::load_matrix_sync(bf[j], &Bs[wc2 * 32 + j * 16][ks], 20);
#pragma unroll
                for (int e = 0; e < bf[j].num_elements; e++)
                    bf[j].x[e] = wmma::__float_to_tf32(bf[j].x[e]);
            }
#pragma unroll
            for (int i = 0; i < 2; i++)
#pragma unroll
                for (int j = 0; j < 2; j++)
                    wmma::mma_sync(acc[i][j], af[i], bf[j], acc[i][j]);
        }
        __syncthreads();
    }

#pragma unroll
    for (int i = 0; i < 2; i++)
#pragma unroll
        for (int j = 0; j < 2; j++)
            wmma::store_matrix_sync(&Cs[wr2 * 32 + i * 16][wc2 * 32 + j * 16], acc[i][j],
                                    64, wmma::mem_row_major);
    __syncthreads();

    float* dst = out + (size_t)(by * 64) * 768 + n0;
    for (int i = tid; i < 1024; i += 128) {
        int rr = i >> 4;
        int cc = (i & 15) << 2;
        float4 v = *(float4*)&Cs[rr][cc];
        v.x += bias[n0 + cc + 0];
        v.y += bias[n0 + cc + 1];
        v.z += bias[n0 + cc + 2];
        v.w += bias[n0 + cc + 3];
        *(float4*)(dst + (size_t)rr * 768 + cc) = v;
    }
}

// ---------------------------------------------------------------------------
extern "C" void kernel_launch(void* const* d_in, const int* in_sizes, int n_in,
                              void* d_out, int out_size) {
    const float* x      = (const float*)d_in[0];
    const float* qkv_w  = (const float*)d_in[1];
    const float* proj_w = (const float*)d_in[2];
    const float* proj_b = (const float*)d_in[3];
    float* out = (float*)d_out;

    cudaFuncSetAttribute(attn_tc, cudaFuncAttributeMaxDynamicSharedMemorySize, 91136);

    dim3 g1(36, 512);
    qkv_gemm<<<g1, 128>>>(x, qkv_w);

    attn_tc<<<3072, 128, 91136>>>();

    dim3 g2(12, 512);
    proj_gemm<<<g2, 128>>>(proj_w, proj_b, out);
}